// round 4
// baseline (speedup 1.0000x reference)
#include <cuda_runtime.h>
#include <cstdint>
#include <cstddef>

#define BB   2
#define LL   512
#define HIN  1024
#define ENT  16
#define DD   50
#define TOT  850
#define PADN 896
#define NMASK 511
#define SCALE 0.14142135623730951f

// Scratch (device globals; no allocation allowed)
__device__ float g_Wp[2 * HIN * PADN];
__device__ float g_proj_s[BB * ENT * LL * DD];   // [b][e][l][d], e<16 only
__device__ float g_proj_e[BB * ENT * LL * DD];
__device__ float g_conj_s[BB * LL * DD];         // e=16 slice, [b*L+l][d]
__device__ float g_conj_e[BB * LL * DD];
__device__ float g_cd[BB * NMASK];
__device__ float g_fm[BB * LL * LL];             // final_mask scratch (2MB)
__device__ float g_tcos[LL * (DD / 2)];
__device__ float g_tsin[LL * (DD / 2)];

// ---------------------------------------------------------------------------
// Kernel 0: pad W into [1024][896]
// ---------------------------------------------------------------------------
__global__ void pad_w(const float* __restrict__ W0, const float* __restrict__ W1)
{
    int idx = blockIdx.x * blockDim.x + threadIdx.x;
    const int total = 2 * HIN * PADN;
    if (idx >= total) return;
    int z = idx / (HIN * PADN);
    int r = idx - z * (HIN * PADN);
    int k = r / PADN, n = r - (r / PADN) * PADN;
    const float* W = z ? W1 : W0;
    g_Wp[idx] = (n < TOT) ? W[(size_t)k * TOT + n] : 0.f;
}

// ---------------------------------------------------------------------------
// Kernel 0b: RoPE trig table (fp64, once)
// ---------------------------------------------------------------------------
__global__ void trig_table()
{
    int idx = blockIdx.x * blockDim.x + threadIdx.x;
    if (idx >= LL * (DD / 2)) return;
    int l = idx / (DD / 2), t = idx - l * (DD / 2);
    double inv = exp(-((2.0 * t) / (double)DD) * log(10000.0));
    double ang = (double)l * inv;
    g_tcos[idx] = (float)cos(ang);
    g_tsin[idx] = (float)sin(ang);
}

// ---------------------------------------------------------------------------
// Kernel 1: tiny projection — e=16 columns only (cols 800..849), both z.
// grid (128 m-tiles of 8 rows, 2 z), 128 threads.
// ---------------------------------------------------------------------------
__global__ __launch_bounds__(128) void tiny_proj(
    const float* __restrict__ X,
    const float* __restrict__ bias0, const float* __restrict__ bias1)
{
    const int z = blockIdx.y;
    const int m0 = blockIdx.x * 8;
    const float* Wp  = g_Wp + (size_t)z * HIN * PADN;
    const float* bias = z ? bias1 : bias0;
    float* dst       = z ? g_conj_e : g_conj_s;

    __shared__ float Xt[32][8];     // [kk][r]
    __shared__ float Wt[32][64];    // [kk][d], cols 50..63 zero-filled

    const int tid = threadIdx.x;
    const int r  = tid >> 4;        // 0..7
    const int cg = tid & 15;        // col group (cg*4 .. cg*4+3)

    float acc0 = 0.f, acc1 = 0.f, acc2 = 0.f, acc3 = 0.f;

    for (int kc = 0; kc < HIN; kc += 32) {
        // load X tile (threads 0..63)
        if (tid < 64) {
            int row = tid >> 3;
            int ks  = (tid & 7) * 4;
            float4 v = *reinterpret_cast<const float4*>(
                X + (size_t)(m0 + row) * HIN + kc + ks);
            Xt[ks + 0][row] = v.x; Xt[ks + 1][row] = v.y;
            Xt[ks + 2][row] = v.z; Xt[ks + 3][row] = v.w;
        }
        // load W slice (32 x 64, cols >= 50 zero)
        for (int x = tid; x < 32 * 64; x += 128) {
            int kk = x >> 6, d = x & 63;
            Wt[kk][d] = (d < DD) ? Wp[(size_t)(kc + kk) * PADN + 800 + d] : 0.f;
        }
        __syncthreads();
        #pragma unroll
        for (int kk = 0; kk < 32; kk++) {
            float xv = Xt[kk][r];
            float4 w = *reinterpret_cast<const float4*>(&Wt[kk][cg * 4]);
            acc0 = fmaf(xv, w.x, acc0);
            acc1 = fmaf(xv, w.y, acc1);
            acc2 = fmaf(xv, w.z, acc2);
            acc3 = fmaf(xv, w.w, acc3);
        }
        __syncthreads();
    }
    const float a[4] = {acc0, acc1, acc2, acc3};
    #pragma unroll
    for (int i = 0; i < 4; i++) {
        int d = cg * 4 + i;
        if (d < DD)
            dst[(size_t)(m0 + r) * DD + d] = a[i] + bias[800 + d];
    }
}

// ---------------------------------------------------------------------------
// Kernel 2: conj_diag
// ---------------------------------------------------------------------------
__global__ void conj_kernel()
{
    int t = blockIdx.x * blockDim.x + threadIdx.x;
    if (t >= BB * NMASK) return;
    int b = t / NMASK, i = t - (t / NMASK) * NMASK;
    const float* a = g_conj_s + ((size_t)b * LL + i) * DD;
    const float* c = g_conj_e + ((size_t)b * LL + i + 1) * DD;
    float s = 0.f;
    #pragma unroll
    for (int d = 0; d < DD; d++) s = fmaf(a[d], c[d], s);
    g_cd[t] = s * SCALE;
}

// ---------------------------------------------------------------------------
// Megakernel: 416 GEMM blocks (cols 0..799) + 512 mask-stream blocks,
// interleaved by bid so wave-1 mixes FMA-bound and DRAM-bound work.
// 128 threads everywhere.
// ---------------------------------------------------------------------------
struct MegaSmem {
    union {
        struct { float As[2][16][68]; float Bs[2][16][68]; } g;  // 17408 B
        float scd[BB * NMASK];                                    // 4088 B
    } u;
};

__device__ __forceinline__ void gemm_block(
    int idx, const float* __restrict__ X,
    const float* __restrict__ bias0, const float* __restrict__ bias1,
    MegaSmem* sm)
{
    const int z  = idx / 208;
    const int r  = idx - z * 208;
    const int nt = r % 13;
    const int mt = r / 13;
    const int n0 = nt * 64, m0 = mt * 64;

    const float* Wp   = g_Wp + (size_t)z * HIN * PADN;
    const float* bias = z ? bias1 : bias0;
    float* dst        = z ? g_proj_e : g_proj_s;

    float (*As)[16][68] = sm->u.g.As;
    float (*Bs)[16][68] = sm->u.g.Bs;

    const int tid = threadIdx.x;
    const int am = tid >> 1, ak = (tid & 1) * 8;
    const int bk = tid >> 3, bn = (tid & 7) * 4;

    const float* Aptr = X  + (size_t)(m0 + am) * HIN + ak;
    const float* Bptr = Wp + (size_t)bk * PADN + n0 + bn;

    float4 ra0 = *reinterpret_cast<const float4*>(Aptr);
    float4 ra1 = *reinterpret_cast<const float4*>(Aptr + 4);
    float4 rb0 = *reinterpret_cast<const float4*>(Bptr);
    float4 rb1 = *reinterpret_cast<const float4*>(Bptr + 32);

    As[0][ak + 0][am] = ra0.x; As[0][ak + 1][am] = ra0.y;
    As[0][ak + 2][am] = ra0.z; As[0][ak + 3][am] = ra0.w;
    As[0][ak + 4][am] = ra1.x; As[0][ak + 5][am] = ra1.y;
    As[0][ak + 6][am] = ra1.z; As[0][ak + 7][am] = ra1.w;
    *reinterpret_cast<float4*>(&Bs[0][bk][bn])      = rb0;
    *reinterpret_cast<float4*>(&Bs[0][bk][bn + 32]) = rb1;
    __syncthreads();

    float acc[4][8];
    #pragma unroll
    for (int i = 0; i < 4; i++)
        #pragma unroll
        for (int j = 0; j < 8; j++) acc[i][j] = 0.f;

    const int ty = tid >> 3, tx = tid & 7;

    for (int t = 0; t < 64; t++) {
        const int cur = t & 1;
        if (t < 63) {
            ra0 = *reinterpret_cast<const float4*>(Aptr + (t + 1) * 16);
            ra1 = *reinterpret_cast<const float4*>(Aptr + (t + 1) * 16 + 4);
            rb0 = *reinterpret_cast<const float4*>(Bptr + (size_t)(t + 1) * 16 * PADN);
            rb1 = *reinterpret_cast<const float4*>(Bptr + (size_t)(t + 1) * 16 * PADN + 32);
        }
        #pragma unroll
        for (int kk = 0; kk < 16; kk++) {
            float4 av  = *reinterpret_cast<const float4*>(&As[cur][kk][ty * 4]);
            float4 bva = *reinterpret_cast<const float4*>(&Bs[cur][kk][tx * 8]);
            float4 bvb = *reinterpret_cast<const float4*>(&Bs[cur][kk][tx * 8 + 4]);
            const float a4[4] = {av.x, av.y, av.z, av.w};
            const float b8[8] = {bva.x, bva.y, bva.z, bva.w,
                                 bvb.x, bvb.y, bvb.z, bvb.w};
            #pragma unroll
            for (int i = 0; i < 4; i++)
                #pragma unroll
                for (int j = 0; j < 8; j++)
                    acc[i][j] = fmaf(a4[i], b8[j], acc[i][j]);
        }
        if (t < 63) {
            const int nxt = cur ^ 1;
            As[nxt][ak + 0][am] = ra0.x; As[nxt][ak + 1][am] = ra0.y;
            As[nxt][ak + 2][am] = ra0.z; As[nxt][ak + 3][am] = ra0.w;
            As[nxt][ak + 4][am] = ra1.x; As[nxt][ak + 5][am] = ra1.y;
            As[nxt][ak + 6][am] = ra1.z; As[nxt][ak + 7][am] = ra1.w;
            *reinterpret_cast<float4*>(&Bs[nxt][bk][bn])      = rb0;
            *reinterpret_cast<float4*>(&Bs[nxt][bk][bn + 32]) = rb1;
            __syncthreads();
        }
    }

    #pragma unroll
    for (int i = 0; i < 4; i++) {
        int row = m0 + ty * 4 + i;
        int bb = row >> 9, l = row & 511;
        #pragma unroll
        for (int j = 0; j < 8; j++) {
            int col = n0 + tx * 8 + j;
            if (col < 800) {               // e < 16 only
                int e = col / DD;
                int d = col - e * DD;
                dst[(((size_t)bb * ENT + e) * LL + l) * DD + d] =
                    acc[i][j] + bias[col];
            }
        }
    }
}

__device__ __forceinline__ void mask_block(
    int idx, const float* __restrict__ mask, MegaSmem* sm)
{
    const int tid = threadIdx.x;
    float* scd = sm->u.scd;
    for (int k = tid; k < BB * NMASK; k += 128) scd[k] = g_cd[k];
    __syncthreads();

    const int jt = idx & 15, it = idx >> 4;       // idx 0..511
    const int j0 = jt * 32, i0 = it * 16;
    const int ty = tid >> 3, tx = tid & 7;
    const int i = i0 + ty, jq = j0 + tx * 4;
    const float* mp = mask + (size_t)i * LL + jq;

    float4 a0 = make_float4(0.f, 0.f, 0.f, 0.f);
    float4 a1 = make_float4(0.f, 0.f, 0.f, 0.f);

    int k = 0;
    for (; k + 8 <= NMASK; k += 8) {
        float4 m[8];
        #pragma unroll
        for (int u = 0; u < 8; u++)
            m[u] = *reinterpret_cast<const float4*>(mp + (size_t)(k + u) * (LL * LL));
        #pragma unroll
        for (int u = 0; u < 8; u++) {
            float c0 = scd[k + u], c1 = scd[NMASK + k + u];
            a0.x = fmaf(c0, m[u].x, a0.x); a0.y = fmaf(c0, m[u].y, a0.y);
            a0.z = fmaf(c0, m[u].z, a0.z); a0.w = fmaf(c0, m[u].w, a0.w);
            a1.x = fmaf(c1, m[u].x, a1.x); a1.y = fmaf(c1, m[u].y, a1.y);
            a1.z = fmaf(c1, m[u].z, a1.z); a1.w = fmaf(c1, m[u].w, a1.w);
        }
    }
    for (; k < NMASK; k++) {
        float4 m = *reinterpret_cast<const float4*>(mp + (size_t)k * (LL * LL));
        float c0 = scd[k], c1 = scd[NMASK + k];
        a0.x = fmaf(c0, m.x, a0.x); a0.y = fmaf(c0, m.y, a0.y);
        a0.z = fmaf(c0, m.z, a0.z); a0.w = fmaf(c0, m.w, a0.w);
        a1.x = fmaf(c1, m.x, a1.x); a1.y = fmaf(c1, m.y, a1.y);
        a1.z = fmaf(c1, m.z, a1.z); a1.w = fmaf(c1, m.w, a1.w);
    }

    *reinterpret_cast<float4*>(g_fm + (size_t)i * LL + jq)            = a0;
    *reinterpret_cast<float4*>(g_fm + (size_t)(LL + i) * LL + jq)     = a1;
}

__global__ __launch_bounds__(128) void mega_kernel(
    const float* __restrict__ X, const float* __restrict__ mask,
    const float* __restrict__ bias0, const float* __restrict__ bias1)
{
    __shared__ MegaSmem sm;
    const int bid = blockIdx.x;
    if (bid < 832) {
        if (bid & 1) mask_block(bid >> 1, mask, &sm);
        else         gemm_block(bid >> 1, X, bias0, bias1, &sm);
    } else {
        mask_block(416 + (bid - 832), mask, &sm);
    }
}

// ---------------------------------------------------------------------------
// RoPE apply (table lookup)
// ---------------------------------------------------------------------------
__global__ void rope_apply()
{
    int idx = blockIdx.x * blockDim.x + threadIdx.x;
    const int total = 2 * BB * ENT * LL * (DD / 2);
    if (idx >= total) return;

    int t = idx % (DD / 2); int r = idx / (DD / 2);
    int l = r % LL;          r /= LL;
    int e = r % ENT;         r /= ENT;
    int b = r % BB;          r /= BB;
    float* p = r ? g_proj_e : g_proj_s;

    float c = g_tcos[l * (DD / 2) + t];
    float s = g_tsin[l * (DD / 2) + t];

    size_t base = (((size_t)b * ENT + e) * LL + l) * DD + 2 * t;
    float2 v = *reinterpret_cast<float2*>(&p[base]);
    float2 o;
    o.x = v.x * c - v.y * s;
    o.y = v.y * c + v.x * s;
    *reinterpret_cast<float2*>(&p[base]) = o;
}

// ---------------------------------------------------------------------------
// Scores kernel: out[b,i,j,e] = scale*q·k + g_fm[b,i,j]
// grid (8 j-tiles of 64, 32 i-tiles of 16, 2 e-halves of 8), 256 threads.
// ---------------------------------------------------------------------------
__global__ __launch_bounds__(256) void scores_kernel(float* __restrict__ out)
{
    __shared__ float skT[DD * 64];
    __shared__ float sqT[DD * 16];

    const int tid = threadIdx.x;
    const int tx = tid & 15, ty = tid >> 4;
    const int j0 = blockIdx.x * 64, i0 = blockIdx.y * 16;
    const int eh = blockIdx.z * 8;
    const int i = i0 + ty;

    for (int b = 0; b < BB; b++) {
        float4 fm = *reinterpret_cast<const float4*>(
            g_fm + ((size_t)b * LL + i) * LL + j0 + tx * 4);
        float sreg[8][4];

        #pragma unroll 1
        for (int e8 = 0; e8 < 8; e8++) {
            int e = eh + e8;
            __syncthreads();
            const float* qb = g_proj_s + (((size_t)b * ENT + e) * LL + i0) * DD;
            const float* kb = g_proj_e + (((size_t)b * ENT + e) * LL + j0) * DD;
            for (int x = tid; x < 16 * DD; x += 256) {
                int ii = x / DD, d = x - ii * DD;
                sqT[d * 16 + ii] = qb[x];
            }
            for (int x = tid; x < 64 * DD; x += 256) {
                int jj = x / DD, d = x - jj * DD;
                skT[d * 64 + jj] = kb[x];
            }
            __syncthreads();
            float r0 = 0.f, r1 = 0.f, r2 = 0.f, r3 = 0.f;
            #pragma unroll
            for (int d = 0; d < DD; d++) {
                float q = sqT[d * 16 + ty];
                float4 kv = *reinterpret_cast<const float4*>(&skT[d * 64 + tx * 4]);
                r0 = fmaf(q, kv.x, r0);
                r1 = fmaf(q, kv.y, r1);
                r2 = fmaf(q, kv.z, r2);
                r3 = fmaf(q, kv.w, r3);
            }
            sreg[e8][0] = r0 * SCALE; sreg[e8][1] = r1 * SCALE;
            sreg[e8][2] = r2 * SCALE; sreg[e8][3] = r3 * SCALE;
        }

        const float a[4] = {fm.x, fm.y, fm.z, fm.w};
        #pragma unroll
        for (int jj = 0; jj < 4; jj++) {
            int j = j0 + tx * 4 + jj;
            float* op = out + ((((size_t)b * LL + i) * LL + j) * ENT) + eh;
            *reinterpret_cast<float4*>(op) =
                make_float4(sreg[0][jj] + a[jj], sreg[1][jj] + a[jj],
                            sreg[2][jj] + a[jj], sreg[3][jj] + a[jj]);
            *reinterpret_cast<float4*>(op + 4) =
                make_float4(sreg[4][jj] + a[jj], sreg[5][jj] + a[jj],
                            sreg[6][jj] + a[jj], sreg[7][jj] + a[jj]);
        }
    }
}

// ---------------------------------------------------------------------------
extern "C" void kernel_launch(void* const* d_in, const int* in_sizes, int n_in,
                              void* d_out, int out_size)
{
    const float* X    = (const float*)d_in[0];
    const float* mask = (const float*)d_in[1];
    const float* Ws   = (const float*)d_in[2];
    const float* bs   = (const float*)d_in[3];
    const float* We   = (const float*)d_in[4];
    const float* be   = (const float*)d_in[5];
    float* out        = (float*)d_out;

    {
        const int total = 2 * HIN * PADN;
        pad_w<<<(total + 255) / 256, 256>>>(Ws, We);
    }
    trig_table<<<(LL * (DD / 2) + 255) / 256, 256>>>();

    tiny_proj<<<dim3(LL * BB / 8, 2), 128>>>(X, bs, be);
    conj_kernel<<<(BB * NMASK + 255) / 256, 256>>>();

    mega_kernel<<<928, 128>>>(X, mask, bs, be);

    {
        const int total = 2 * BB * ENT * LL * (DD / 2);
        rope_apply<<<(total + 255) / 256, 256>>>();
    }

    scores_kernel<<<dim3(8, 32, 2), 256>>>(out);
}

// round 6
// speedup vs baseline: 1.4293x; 1.4293x over previous
#include <cuda_runtime.h>
#include <cuda_bf16.h>
#include <mma.h>
#include <cstdint>
#include <cstddef>

using namespace nvcuda;

#define BB   2
#define LL   512
#define HIN  1024
#define ENT  16
#define DD   50
#define TOT  850
#define PADN 896
#define NMASK 511
#define SCALE 0.14142135623730951f

// ---------------------------------------------------------------------------
// Scratch (device globals)
// ---------------------------------------------------------------------------
__device__ __nv_bfloat16 g_Xh[1024 * 1024];
__device__ __nv_bfloat16 g_Xl[1024 * 1024];
__device__ __nv_bfloat16 g_WhT[2 * PADN * HIN];   // [z][n][k]
__device__ __nv_bfloat16 g_WlT[2 * PADN * HIN];
__device__ float g_proj_s[BB * (ENT + 1) * LL * DD];
__device__ float g_proj_e[BB * (ENT + 1) * LL * DD];
__device__ float g_cd[BB * NMASK];
__device__ float g_tcos[LL * (DD / 2)];
__device__ float g_tsin[LL * (DD / 2)];

// ---------------------------------------------------------------------------
// Prep kernels
// ---------------------------------------------------------------------------
__global__ void split_x(const float* __restrict__ X)
{
    int idx = blockIdx.x * blockDim.x + threadIdx.x;
    if (idx >= 1024 * 1024) return;
    float x = X[idx];
    __nv_bfloat16 h = __float2bfloat16(x);
    __nv_bfloat16 l = __float2bfloat16(x - __bfloat162float(h));
    g_Xh[idx] = h;
    g_Xl[idx] = l;
}

// transpose + split W[k][n] -> WhT/WlT[z][n][k], zero pad n>=850
__global__ void split_wT(const float* __restrict__ W0, const float* __restrict__ W1)
{
    __shared__ __nv_bfloat16 th[32][33];
    __shared__ __nv_bfloat16 tl[32][33];
    const int z = blockIdx.z;
    const float* W = z ? W1 : W0;
    const int n0 = blockIdx.x * 32;
    const int k0 = blockIdx.y * 32;
    const int tx = threadIdx.x, ty = threadIdx.y;

    int n = n0 + tx, k = k0 + ty;
    float x = (n < TOT) ? W[(size_t)k * TOT + n] : 0.f;
    __nv_bfloat16 h = __float2bfloat16(x);
    __nv_bfloat16 l = __float2bfloat16(x - __bfloat162float(h));
    th[ty][tx] = h;
    tl[ty][tx] = l;
    __syncthreads();

    int on = n0 + ty, ok = k0 + tx;
    size_t oidx = (size_t)z * PADN * HIN + (size_t)on * HIN + ok;
    g_WhT[oidx] = th[tx][ty];
    g_WlT[oidx] = tl[tx][ty];
}

__global__ void trig_table()
{
    int idx = blockIdx.x * blockDim.x + threadIdx.x;
    if (idx >= LL * (DD / 2)) return;
    int l = idx / (DD / 2), t = idx - l * (DD / 2);
    double inv = exp(-((2.0 * t) / (double)DD) * log(10000.0));
    double ang = (double)l * inv;
    g_tcos[idx] = (float)cos(ang);
    g_tsin[idx] = (float)sin(ang);
}

// ---------------------------------------------------------------------------
// WMMA bf16 GEMM (HMMA path — tcgen05 not reachable from compute_103 PTX).
// Block: 256 thr / 8 warps, tile M128 x N64, K staged 32.
// 3-term split: Ah*Bh + Ah*Bl + Al*Bh, fp32 accum.
// grid (14, 8, 2).
// ---------------------------------------------------------------------------
union GemmSmem {
    struct {
        __nv_bfloat16 Ah[128][40];
        __nv_bfloat16 Al[128][40];
        __nv_bfloat16 Bh[64][40];
        __nv_bfloat16 Bl[64][40];
    } t;
    float out[128][68];
};

__global__ __launch_bounds__(256) void gemm_wmma(
    const float* __restrict__ bias0, const float* __restrict__ bias1)
{
    __shared__ GemmSmem sm;

    const int z  = blockIdx.z;
    const int n0 = blockIdx.x * 64;
    const int m0 = blockIdx.y * 128;
    const float* bias = z ? bias1 : bias0;
    float* dst        = z ? g_proj_e : g_proj_s;

    const int tid = threadIdx.x;
    const int wid = tid >> 5;
    const int wr = wid >> 1;       // 0..3 -> M chunk of 32
    const int wc = wid & 1;        // 0..1 -> N chunk of 32

    const uint4* Xh4 = reinterpret_cast<const uint4*>(g_Xh);
    const uint4* Xl4 = reinterpret_cast<const uint4*>(g_Xl);
    const uint4* Bh4 = reinterpret_cast<const uint4*>(g_WhT) + (size_t)z * PADN * 128;
    const uint4* Bl4 = reinterpret_cast<const uint4*>(g_WlT) + (size_t)z * PADN * 128;

    wmma::fragment<wmma::accumulator, 16, 16, 16, float> c[2][2];
    #pragma unroll
    for (int i = 0; i < 2; i++)
        #pragma unroll
        for (int j = 0; j < 2; j++)
            wmma::fill_fragment(c[i][j], 0.f);

    for (int kc = 0; kc < HIN; kc += 32) {
        const int kc8 = kc >> 3;
        // A tiles: 128 rows x 4 uint4; 512 uint4 per matrix; 2 per thread
        #pragma unroll
        for (int it = 0; it < 2; it++) {
            int u = it * 256 + tid;
            int row = u >> 2, c8 = u & 3;
            size_t gi = (size_t)(m0 + row) * 128 + kc8 + c8;
            *reinterpret_cast<uint4*>(&sm.t.Ah[row][c8 * 8]) = Xh4[gi];
            *reinterpret_cast<uint4*>(&sm.t.Al[row][c8 * 8]) = Xl4[gi];
        }
        // B tiles: 64 rows x 4 uint4 = 256 uint4; 1 per thread
        {
            int row = tid >> 2, c8 = tid & 3;
            size_t gi = (size_t)(n0 + row) * 128 + kc8 + c8;
            *reinterpret_cast<uint4*>(&sm.t.Bh[row][c8 * 8]) = Bh4[gi];
            *reinterpret_cast<uint4*>(&sm.t.Bl[row][c8 * 8]) = Bl4[gi];
        }
        __syncthreads();

        #pragma unroll
        for (int ks = 0; ks < 32; ks += 16) {
            wmma::fragment<wmma::matrix_a, 16, 16, 16, __nv_bfloat16, wmma::row_major> ah[2], al[2];
            wmma::fragment<wmma::matrix_b, 16, 16, 16, __nv_bfloat16, wmma::col_major> bh[2], bl[2];
            #pragma unroll
            for (int i = 0; i < 2; i++) {
                wmma::load_matrix_sync(ah[i], &sm.t.Ah[wr * 32 + i * 16][ks], 40);
                wmma::load_matrix_sync(al[i], &sm.t.Al[wr * 32 + i * 16][ks], 40);
            }
            #pragma unroll
            for (int j = 0; j < 2; j++) {
                wmma::load_matrix_sync(bh[j], &sm.t.Bh[wc * 32 + j * 16][ks], 40);
                wmma::load_matrix_sync(bl[j], &sm.t.Bl[wc * 32 + j * 16][ks], 40);
            }
            #pragma unroll
            for (int i = 0; i < 2; i++)
                #pragma unroll
                for (int j = 0; j < 2; j++) {
                    wmma::mma_sync(c[i][j], ah[i], bh[j], c[i][j]);
                    wmma::mma_sync(c[i][j], ah[i], bl[j], c[i][j]);
                    wmma::mma_sync(c[i][j], al[i], bh[j], c[i][j]);
                }
        }
        __syncthreads();
    }

    // Epilogue: frags -> smem float -> guarded scatter with bias
    #pragma unroll
    for (int i = 0; i < 2; i++)
        #pragma unroll
        for (int j = 0; j < 2; j++)
            wmma::store_matrix_sync(&sm.out[wr * 32 + i * 16][wc * 32 + j * 16],
                                    c[i][j], 68, wmma::mem_row_major);
    __syncthreads();

    for (int idx = tid; idx < 128 * 64; idx += 256) {
        int row = idx >> 6, col = idx & 63;
        int n = n0 + col;
        if (n < TOT) {
            int e = n / DD, d = n - e * DD;
            int m = m0 + row;
            int b = m >> 9, l = m & 511;
            dst[(((size_t)b * (ENT + 1) + e) * LL + l) * DD + d] =
                sm.out[row][col] + bias[n];
        }
    }
}

// ---------------------------------------------------------------------------
// RoPE apply (table lookup, e<16)
// ---------------------------------------------------------------------------
__global__ void rope_apply()
{
    int idx = blockIdx.x * blockDim.x + threadIdx.x;
    const int total = 2 * BB * ENT * LL * (DD / 2);
    if (idx >= total) return;

    int t = idx % (DD / 2); int r = idx / (DD / 2);
    int l = r % LL;          r /= LL;
    int e = r % ENT;         r /= ENT;
    int b = r % BB;          r /= BB;
    float* p = r ? g_proj_e : g_proj_s;

    float c = g_tcos[l * (DD / 2) + t];
    float s = g_tsin[l * (DD / 2) + t];

    size_t base = (((size_t)b * (ENT + 1) + e) * LL + l) * DD + 2 * t;
    float2 v = *reinterpret_cast<float2*>(&p[base]);
    float2 o;
    o.x = v.x * c - v.y * s;
    o.y = v.y * c + v.x * s;
    *reinterpret_cast<float2*>(&p[base]) = o;
}

// ---------------------------------------------------------------------------
// conj_diag
// ---------------------------------------------------------------------------
__global__ void conj_kernel()
{
    int t = blockIdx.x * blockDim.x + threadIdx.x;
    if (t >= BB * NMASK) return;
    int b = t / NMASK, i = t - (t / NMASK) * NMASK;
    const float* a = g_proj_s + (((size_t)b * (ENT + 1) + ENT) * LL + i) * DD;
    const float* c = g_proj_e + (((size_t)b * (ENT + 1) + ENT) * LL + (i + 1)) * DD;
    float s = 0.f;
    #pragma unroll
    for (int d = 0; d < DD; d++) s = fmaf(a[d], c[d], s);
    g_cd[t] = s * SCALE;
}

// ---------------------------------------------------------------------------
// Fused mask-reduction + scores (round-2 proven version)
// ---------------------------------------------------------------------------
struct FusedSmem {
    float skT[DD * 64];
    float sqT[DD * 16];
    float scd[BB * NMASK];
};

__device__ __forceinline__ void mask_phase(
    const float* __restrict__ mp, const float* __restrict__ scd,
    float4& a0, float4& a1)
{
    int k = 0;
    for (; k + 8 <= NMASK; k += 8) {
        float4 m[8];
        #pragma unroll
        for (int u = 0; u < 8; u++)
            m[u] = *reinterpret_cast<const float4*>(mp + (size_t)(k + u) * (LL * LL));
        #pragma unroll
        for (int u = 0; u < 8; u++) {
            float c0 = scd[k + u], c1 = scd[NMASK + k + u];
            a0.x = fmaf(c0, m[u].x, a0.x); a0.y = fmaf(c0, m[u].y, a0.y);
            a0.z = fmaf(c0, m[u].z, a0.z); a0.w = fmaf(c0, m[u].w, a0.w);
            a1.x = fmaf(c1, m[u].x, a1.x); a1.y = fmaf(c1, m[u].y, a1.y);
            a1.z = fmaf(c1, m[u].z, a1.z); a1.w = fmaf(c1, m[u].w, a1.w);
        }
    }
    for (; k < NMASK; k++) {
        float4 m = *reinterpret_cast<const float4*>(mp + (size_t)k * (LL * LL));
        float c0 = scd[k], c1 = scd[NMASK + k];
        a0.x = fmaf(c0, m.x, a0.x); a0.y = fmaf(c0, m.y, a0.y);
        a0.z = fmaf(c0, m.z, a0.z); a0.w = fmaf(c0, m.w, a0.w);
        a1.x = fmaf(c1, m.x, a1.x); a1.y = fmaf(c1, m.y, a1.y);
        a1.z = fmaf(c1, m.z, a1.z); a1.w = fmaf(c1, m.w, a1.w);
    }
}

__device__ __forceinline__ void score_pass(
    FusedSmem* sm, int b, int i0, int j0, int tid, int tx, int ty,
    float sreg[ENT][4])
{
    #pragma unroll 1
    for (int e = 0; e < ENT; e++) {
        __syncthreads();
        const float* qb = g_proj_s + (((size_t)b * (ENT + 1) + e) * LL + i0) * DD;
        const float* kb = g_proj_e + (((size_t)b * (ENT + 1) + e) * LL + j0) * DD;
        for (int x = tid; x < 16 * DD; x += 256) {
            int ii = x / DD, d = x - ii * DD;
            sm->sqT[d * 16 + ii] = qb[x];
        }
        for (int x = tid; x < 64 * DD; x += 256) {
            int jj = x / DD, d = x - jj * DD;
            sm->skT[d * 64 + jj] = kb[x];
        }
        __syncthreads();
        float r0 = 0.f, r1 = 0.f, r2 = 0.f, r3 = 0.f;
        #pragma unroll
        for (int d = 0; d < DD; d++) {
            float q = sm->sqT[d * 16 + ty];
            float4 kv = *reinterpret_cast<const float4*>(&sm->skT[d * 64 + tx * 4]);
            r0 = fmaf(q, kv.x, r0);
            r1 = fmaf(q, kv.y, r1);
            r2 = fmaf(q, kv.z, r2);
            r3 = fmaf(q, kv.w, r3);
        }
        sreg[e][0] = r0 * SCALE; sreg[e][1] = r1 * SCALE;
        sreg[e][2] = r2 * SCALE; sreg[e][3] = r3 * SCALE;
    }
}

__device__ __forceinline__ void store_b(
    float* __restrict__ out, int b, int i, int j0, int tx,
    const float sreg[ENT][4], const float4& am)
{
    const float a[4] = {am.x, am.y, am.z, am.w};
    #pragma unroll
    for (int jj = 0; jj < 4; jj++) {
        float4* op = reinterpret_cast<float4*>(
            out + ((((size_t)b * LL + i) * LL + (j0 + tx * 4 + jj)) * ENT));
        #pragma unroll
        for (int v = 0; v < 4; v++)
            op[v] = make_float4(sreg[4 * v + 0][jj] + a[jj],
                                sreg[4 * v + 1][jj] + a[jj],
                                sreg[4 * v + 2][jj] + a[jj],
                                sreg[4 * v + 3][jj] + a[jj]);
    }
}

__global__ __launch_bounds__(256) void fused_kernel(
    const float* __restrict__ mask, float* __restrict__ out)
{
    __shared__ FusedSmem sm;
    const int tid = threadIdx.x;
    const int tx = tid & 15, ty = tid >> 4;
    const int i0 = blockIdx.y * 16, j0 = blockIdx.x * 64;
    const int i = i0 + ty;

    for (int k = tid; k < BB * NMASK; k += 256) sm.scd[k] = g_cd[k];
    __syncthreads();

    const float* mp = mask + (size_t)i * LL + j0 + tx * 4;
    float4 a0 = make_float4(0.f, 0.f, 0.f, 0.f);
    float4 a1 = make_float4(0.f, 0.f, 0.f, 0.f);
    float sreg[ENT][4];

    if ((blockIdx.x + blockIdx.y) & 1) {
        score_pass(&sm, 0, i0, j0, tid, tx, ty, sreg);
        mask_phase(mp, sm.scd, a0, a1);
        store_b(out, 0, i, j0, tx, sreg, a0);
        score_pass(&sm, 1, i0, j0, tid, tx, ty, sreg);
        store_b(out, 1, i, j0, tx, sreg, a1);
    } else {
        mask_phase(mp, sm.scd, a0, a1);
        score_pass(&sm, 0, i0, j0, tid, tx, ty, sreg);
        store_b(out, 0, i, j0, tx, sreg, a0);
        score_pass(&sm, 1, i0, j0, tid, tx, ty, sreg);
        store_b(out, 1, i, j0, tx, sreg, a1);
    }
}

// ---------------------------------------------------------------------------
extern "C" void kernel_launch(void* const* d_in, const int* in_sizes, int n_in,
                              void* d_out, int out_size)
{
    const float* X    = (const float*)d_in[0];
    const float* mask = (const float*)d_in[1];
    const float* Ws   = (const float*)d_in[2];
    const float* bs   = (const float*)d_in[3];
    const float* We   = (const float*)d_in[4];
    const float* be   = (const float*)d_in[5];
    float* out        = (float*)d_out;

    split_x<<<(1024 * 1024 + 255) / 256, 256>>>(X);
    split_wT<<<dim3(PADN / 32, HIN / 32, 2), dim3(32, 32)>>>(Ws, We);
    trig_table<<<(LL * (DD / 2) + 255) / 256, 256>>>();

    gemm_wmma<<<dim3(PADN / 64, 1024 / 128, 2), 256>>>(bs, be);

    {
        const int total = 2 * BB * ENT * LL * (DD / 2);
        rope_apply<<<(total + 255) / 256, 256>>>();
    }
    conj_kernel<<<(BB * NMASK + 255) / 256, 256>>>();

    fused_kernel<<<dim3(LL / 64, LL / 16), 256>>>(mask, out);
}